// round 11
// baseline (speedup 1.0000x reference)
#include <cuda_runtime.h>
#include <cstdint>

// Problem constants (fixed by reference setup_inputs)
#define NN   4096      // nodes
#define DD   256       // feature dim
#define EE   65536     // directed edges (symmetric list)
#define NW   128       // 4096 bits / 32 = words per adjacency-bitset row
#define MAXC 8         // max cluster size (provably <= 7: each add >= 0.5, cap 3.0)
#define PAD13 0x1FFFu  // 13-bit pad > any node id (max 4095)

// ---------------- device scratch (no allocation allowed) ----------------
__device__ float              g_sraw[EE];
__device__ float              g_score[EE];
__device__ unsigned           g_minb, g_maxb;
__device__ int                g_deg[NN];
__device__ int                g_rowptr[NN + 1];
__device__ int                g_fill[NN];
__device__ int                g_csr[EE];          // edge ids grouped by src, sorted ascending
__device__ float              g_avg[NN];
__device__ unsigned           g_adj[NN * NW];     // adjacency bitset rows
__device__ int                g_mem[NN * MAXC];   // cluster member lists (sorted asc) per seed
__device__ int                g_len[NN];
__device__ unsigned long long g_keyhi[NN];        // packed member list: slots 0..3 (13b each)
__device__ unsigned long long g_keylo[NN];        // slots 4..6
__device__ unsigned char      g_dup[NN];
__device__ int                g_U;
__device__ int                g_Aseed[NN];        // sorted-unique position -> seed index
__device__ int                g_invptr[NN + 1];
__device__ int                g_inv[NN * MAXC];   // node -> list of unique-cluster positions
__device__ int                g_sel[NN];          // selection order -> unique position p
__device__ int                g_K;
__device__ int                g_selmem[NN * MAXC];// selected cluster k -> member list
__device__ int                g_sellen[NN];
__device__ unsigned           g_R[NN * NW];       // per-selected-cluster out-neighborhood bitset
__device__ unsigned char      g_flags[(size_t)NN * NN];  // coarse adjacency [k][l] (K x K used)
__device__ int                g_Enew;

// ---------------- kernels ----------------

__global__ void pk_init() {
    int i = blockIdx.x * blockDim.x + threadIdx.x;
    if (i < NN * NW) g_adj[i] = 0u;
    if (i < NN) { g_deg[i] = 0; g_fill[i] = 0; }
    if (i == 0) {
        g_minb = 0x7f800000u;   // +inf
        g_maxb = 0u;
        g_U = 0; g_K = 0; g_Enew = 0;
    }
}

// warp per edge: L2 distance, degree count, adjacency bit
__global__ void pk_score(const float* __restrict__ x, const int* __restrict__ ei) {
    int gt = blockIdx.x * blockDim.x + threadIdx.x;
    int e = gt >> 5, lane = gt & 31;
    if (e >= EE) return;
    int u = ei[e], v = ei[EE + e];
    const float4* xu = (const float4*)(x + (size_t)u * DD);
    const float4* xv = (const float4*)(x + (size_t)v * DD);
    float acc = 0.f;
#pragma unroll
    for (int t = 0; t < 2; t++) {
        float4 a = xu[lane + 32 * t], b = xv[lane + 32 * t];
        float d0 = a.x - b.x, d1 = a.y - b.y, d2 = a.z - b.z, d3 = a.w - b.w;
        acc += d0 * d0 + d1 * d1 + d2 * d2 + d3 * d3;
    }
#pragma unroll
    for (int o = 16; o; o >>= 1) acc += __shfl_xor_sync(0xffffffffu, acc, o);
    if (lane == 0) {
        float s = __fsqrt_rn(acc + 1e-12f);      // IEEE, immune to fast-math flags
        g_sraw[e] = s;
        unsigned b = __float_as_uint(s);         // s > 0: uint order == float order
        atomicMin(&g_minb, b);
        atomicMax(&g_maxb, b);
        atomicAdd(&g_deg[u], 1);
        atomicOr(&g_adj[u * NW + (v >> 5)], 1u << (v & 31));
    }
}

// one-block 1024-thread exclusive scan of g_deg -> g_rowptr (4 elems/thread)
__global__ void pk_rowptr() {
    __shared__ int s[1024];
    int tid = threadIdx.x;
    int a0 = g_deg[4 * tid], a1 = g_deg[4 * tid + 1];
    int a2 = g_deg[4 * tid + 2], a3 = g_deg[4 * tid + 3];
    int sum = a0 + a1 + a2 + a3;
    s[tid] = sum; __syncthreads();
    for (int o = 1; o < 1024; o <<= 1) {
        int v = (tid >= o) ? s[tid - o] : 0;
        __syncthreads();
        s[tid] += v;
        __syncthreads();
    }
    int excl = s[tid] - sum;
    g_rowptr[4 * tid]     = excl;
    g_rowptr[4 * tid + 1] = excl + a0;
    g_rowptr[4 * tid + 2] = excl + a0 + a1;
    g_rowptr[4 * tid + 3] = excl + a0 + a1 + a2;
    if (tid == 1023) g_rowptr[NN] = excl + sum;
}

// per edge: CSR scatter AND min-max-normalized score (fused; both per-edge passes)
__global__ void pk_scatter(const int* __restrict__ ei) {
    int e = blockIdx.x * blockDim.x + threadIdx.x;
    if (e >= EE) return;
    int u = ei[e];
    int pos = g_rowptr[u] + atomicAdd(&g_fill[u], 1);
    g_csr[pos] = e;
    float mn = __uint_as_float(g_minb), mx = __uint_as_float(g_maxb);
    // exact IEEE ops to match JAX regardless of fast-math flags
    g_score[e] = __fadd_rn(__fdiv_rn(__fsub_rn(g_sraw[e], mn), __fsub_rn(mx, mn)), 0.5f);
}

// per node: sort CSR edge ids ascending (deterministic order), avg score
__global__ void pk_sortavg() {
    int n = blockIdx.x * blockDim.x + threadIdx.x;
    if (n >= NN) return;
    int b = g_rowptr[n], t = g_rowptr[n + 1];
    for (int i = b + 1; i < t; i++) {
        int key = g_csr[i]; int j = i - 1;
        while (j >= b && g_csr[j] > key) { g_csr[j + 1] = g_csr[j]; j--; }
        g_csr[j + 1] = key;
    }
    float s = 0.f;
    for (int i = b; i < t; i++) s += g_score[g_csr[i]];
    // ref avg = (2*sum)/(2*deg) = sum/deg (symmetric list, symmetric distances)
    g_avg[n] = s / (float)(t - b);
}

// warp per seed: Prim-style growth. Candidate = out-edge of cluster with dst outside.
// argmin by (scoreBits, edge id) == JAX argmin first-index semantics.
__global__ void pk_grow(const int* __restrict__ ei) {
    __shared__ int sm[8][MAXC];
    int wid = threadIdx.x >> 5, lane = threadIdx.x & 31;
    int seed = blockIdx.x * 8 + wid;
    if (seed >= NN) return;
    int* M = sm[wid];
    if (lane == 0) M[0] = seed;
    __syncwarp();
    int len = 1;
    float tot = 0.f;
    while (tot < 3.0f && len < MAXC) {
        unsigned long long best = ~0ull;
        for (int m = 0; m < len; m++) {
            int u = M[m];
            int b = g_rowptr[u], t = g_rowptr[u + 1];
            for (int idx = b + lane; idx < t; idx += 32) {
                int e = g_csr[idx];
                int v = ei[EE + e];
                bool in = false;
                for (int mm = 0; mm < len; mm++) if (M[mm] == v) { in = true; break; }
                if (!in) {
                    unsigned long long key =
                        ((unsigned long long)__float_as_uint(g_score[e]) << 32) | (unsigned)e;
                    if (key < best) best = key;
                }
            }
        }
#pragma unroll
        for (int o = 16; o; o >>= 1) {
            unsigned long long oth = __shfl_xor_sync(0xffffffffu, best, o);
            if (oth < best) best = oth;
        }
        if (best == ~0ull) break;                       // no finite candidate
        int e = (int)(best & 0xffffffffu);
        tot += __uint_as_float((unsigned)(best >> 32)); // same accumulation order as ref
        if (lane == 0) M[len] = ei[EE + e];
        __syncwarp();
        len++;
    }
    if (lane == 0) {
        // sort members ascending -> canonical representation
        for (int i = 1; i < len; i++) {
            int k = M[i]; int j = i - 1;
            while (j >= 0 && M[j] > k) { M[j + 1] = M[j]; j--; }
            M[j + 1] = k;
        }
        g_len[seed] = len;
        unsigned long long hi = 0, lo = 0;
#pragma unroll
        for (int sl = 0; sl < 4; sl++)
            hi = (hi << 13) | (sl < len ? (unsigned)M[sl] : PAD13);
#pragma unroll
        for (int sl = 4; sl < 7; sl++)
            lo = (lo << 13) | (sl < len ? (unsigned)M[sl] : PAD13);
        g_keyhi[seed] = hi;
        g_keylo[seed] = lo;
        for (int m = 0; m < MAXC; m++)
            g_mem[seed * MAXC + m] = (m < len) ? M[m] : 0x7fffffff;
    }
}

// np.unique(axis=0) row-lex ascending order == packed-key DESCENDING order:
//  - first differing member: smaller member => True at earlier column => greater row,
//    and => smaller packed key (slot dominates), so row order reverses key order;
//  - prefix case: shorter list pads with 0x1FFF (> any node) => larger key,
//    while the longer list (extra later Trues) is the greater row. Consistent.
__global__ void pk_dup() {
    int i = blockIdx.x * blockDim.x + threadIdx.x;
    if (i >= NN) return;
    unsigned long long hi = g_keyhi[i], lo = g_keylo[i];
    unsigned char d = 0;
    for (int j = 0; j < i; j++)
        if (g_keyhi[j] == hi && g_keylo[j] == lo) { d = 1; break; }
    g_dup[i] = d;
    if (!d) atomicAdd(&g_U, 1);
}

__global__ void pk_rank() {
    int i = blockIdx.x * blockDim.x + threadIdx.x;
    if (i >= NN || g_dup[i]) return;
    unsigned long long hi = g_keyhi[i], lo = g_keylo[i];
    int r = 0;
    for (int j = 0; j < NN; j++) {
        if (g_dup[j]) continue;
        unsigned long long hj = g_keyhi[j];
        if (hj > hi || (hj == hi && g_keylo[j] > lo)) r++;
    }
    g_Aseed[r] = i;   // unique rows in np.unique ascending-lex order
}

// Build inverted index (node -> unique-cluster positions) in ONE single-block
// kernel: shared count -> shared scan -> shared-offset scatter.
__global__ void pk_invbuild() {
    __shared__ int cnt[NN];     // counts, then exclusive offsets
    __shared__ int fill[NN];
    __shared__ int s[1024];
    int tid = threadIdx.x;      // 1024
    int U = g_U;
#pragma unroll
    for (int t = 0; t < 4; t++) { cnt[tid + 1024 * t] = 0; fill[tid + 1024 * t] = 0; }
    __syncthreads();
    for (int p = tid; p < U; p += 1024) {
        int seed = g_Aseed[p], L = g_len[seed];
        for (int m = 0; m < L; m++) atomicAdd(&cnt[g_mem[seed * MAXC + m]], 1);
    }
    __syncthreads();
    int a0 = cnt[4 * tid], a1 = cnt[4 * tid + 1], a2 = cnt[4 * tid + 2], a3 = cnt[4 * tid + 3];
    int sum = a0 + a1 + a2 + a3;
    s[tid] = sum; __syncthreads();
    for (int o = 1; o < 1024; o <<= 1) {
        int v = (tid >= o) ? s[tid - o] : 0;
        __syncthreads();
        s[tid] += v;
        __syncthreads();
    }
    int excl = s[tid] - sum;
    cnt[4 * tid] = excl; cnt[4 * tid + 1] = excl + a0;
    cnt[4 * tid + 2] = excl + a0 + a1; cnt[4 * tid + 3] = excl + a0 + a1 + a2;
    g_invptr[4 * tid] = cnt[4 * tid];         g_invptr[4 * tid + 1] = cnt[4 * tid + 1];
    g_invptr[4 * tid + 2] = cnt[4 * tid + 2]; g_invptr[4 * tid + 3] = cnt[4 * tid + 3];
    if (tid == 1023) g_invptr[NN] = excl + sum;
    __syncthreads();
    for (int p = tid; p < U; p += 1024) {
        int seed = g_Aseed[p], L = g_len[seed];
        for (int m = 0; m < L; m++) {
            int v = g_mem[seed * MAXC + m];
            g_inv[cnt[v] + atomicAdd(&fill[v], 1)] = p;
        }
    }
}

// Sequential greedy max-uncovered-cover with INCREMENTAL packed keys.
// key[p] = (uncovered_count << 13) | (8191 - p): argmax == (count desc, pos asc),
// exactly np.argmax first-index semantics over the ref's count vector.
// Decrement = atomicSub 0x2000. Selected cluster drops to count 0, never re-wins
// while uncovered nodes remain (an uncovered node's own seed cluster is unselected
// and has count >= 1, so a zero-count cluster can never take the argmax).
__global__ void pk_greedy() {
    __shared__ unsigned      s_key[NN];
    __shared__ unsigned char s_cov[NN];
    __shared__ unsigned      s_warp[32];
    __shared__ int           s_unc;
    int tid = threadIdx.x;      // 1024
    int U = g_U;
    for (int i = tid; i < NN; i += 1024) {
        s_key[i] = (i < U) ? (((unsigned)g_len[g_Aseed[i]] << 13) | (8191u - (unsigned)i)) : 0u;
        s_cov[i] = 0;
    }
    if (tid == 0) s_unc = NN;
    __syncthreads();
    int K = 0;
    while (true) {
        unsigned bk = 0;
#pragma unroll
        for (int t = 0; t < 4; t++) {
            unsigned k = s_key[tid + 1024 * t];
            if (k > bk) bk = k;
        }
        bk = __reduce_max_sync(0xffffffffu, bk);
        if ((tid & 31) == 0) s_warp[tid >> 5] = bk;
        __syncthreads();
        if (tid < 32) {
            unsigned v = __reduce_max_sync(0xffffffffu, s_warp[tid]);
            if (tid == 0) s_warp[0] = v;
        }
        __syncthreads();
        int p = 8191 - (int)(s_warp[0] & 8191u);
        if (tid == 0) g_sel[K] = p;
        int seed = g_Aseed[p];
        int L = g_len[seed];
        if (tid < L) {
            int v = g_mem[seed * MAXC + tid];   // members distinct -> no race on s_cov[v]
            if (!s_cov[v]) {
                s_cov[v] = 1;
                atomicSub(&s_unc, 1);
                int b = g_invptr[v], t = g_invptr[v + 1];
                for (int j = b; j < t; j++) atomicSub(&s_key[g_inv[j]], 0x2000u);
            }
        }
        K++;
        __syncthreads();
        if (s_unc == 0 || K >= NN) break;
    }
    if (tid == 0) g_K = K;
}

// Per selected cluster: cache member list + union of members' out-neighborhood bitsets
__global__ void pk_R() {
    int k = blockIdx.x;
    if (k >= g_K) return;
    int seed = g_Aseed[g_sel[k]];
    int L = g_len[seed];
    int w = threadIdx.x;    // 128
    if (w < MAXC) g_selmem[k * MAXC + w] = g_mem[seed * MAXC + w];
    if (w == 0)   g_sellen[k] = L;
    unsigned acc = 0;
    for (int m = 0; m < L; m++) acc |= g_adj[g_mem[seed * MAXC + m] * NW + w];
    g_R[k * NW + w] = acc;
}

// flag[k][l] = clusters adjacent (edge u->v, u in k, v in l), k != l. K x K work only.
// Rk bitset staged in shared: inner probes become conflict-free LDS.
__global__ void pk_flags() {
    __shared__ unsigned Rk[NW];
    int k = blockIdx.x;
    int K = g_K;
    if (k >= K) return;
    if (threadIdx.x < NW) Rk[threadIdx.x] = g_R[k * NW + threadIdx.x];
    __syncthreads();
    for (int l = threadIdx.x; l < K; l += blockDim.x) {
        unsigned char f = 0;
        if (l != k) {
            int L = g_sellen[l];
            for (int m = 0; m < L; m++) {
                int v = g_selmem[l * MAXC + m];
                if ((Rk[v >> 5] >> (v & 31)) & 1u) { f = 1; break; }
            }
        }
        g_flags[((size_t)k << 12) + l] = f;
    }
}

// Single-block: per-row nonzero counts -> shared scan -> emit edge_index_new
// (rows then cols, row-major nonzero order == dense_to_sparse).
__global__ void pk_finalize(float* __restrict__ out) {
    __shared__ int cnt[NN];     // counts, then exclusive offsets
    __shared__ int s[1024];
    int tid = threadIdx.x;      // 1024
    int K = g_K;
#pragma unroll
    for (int t = 0; t < 4; t++) cnt[tid + 1024 * t] = 0;
    __syncthreads();
    for (int k = tid; k < K; k += 1024) {
        const unsigned char* row = &g_flags[(size_t)k << 12];
        int c = 0;
        for (int l = 0; l < K; l++) c += row[l];
        cnt[k] = c;
    }
    __syncthreads();
    int a0 = cnt[4 * tid], a1 = cnt[4 * tid + 1], a2 = cnt[4 * tid + 2], a3 = cnt[4 * tid + 3];
    int sum = a0 + a1 + a2 + a3;
    s[tid] = sum; __syncthreads();
    for (int o = 1; o < 1024; o <<= 1) {
        int v = (tid >= o) ? s[tid - o] : 0;
        __syncthreads();
        s[tid] += v;
        __syncthreads();
    }
    int excl = s[tid] - sum;
    cnt[4 * tid] = excl; cnt[4 * tid + 1] = excl + a0;
    cnt[4 * tid + 2] = excl + a0 + a1; cnt[4 * tid + 3] = excl + a0 + a1 + a2;
    if (tid == 1023) g_Enew = excl + sum;
    __syncthreads();
    int En = g_Enew;   // safe: written before the barrier above
    for (int k = tid; k < K; k += 1024) {
        const unsigned char* row = &g_flags[(size_t)k << 12];
        int pos = cnt[k];
        for (int l = 0; l < K; l++) {
            if (row[l]) {
                out[pos] = (float)k;
                out[En + pos] = (float)l;
                pos++;
            }
        }
    }
}

// x_new[k][d] = sum over members u of avg[u]*x[u][d]   (Ms @ x)
__global__ void pk_xnew(const float* __restrict__ x, float* __restrict__ out) {
    int k = blockIdx.x;
    if (k >= g_K) return;
    int d = threadIdx.x;   // 256
    int L = g_sellen[k];
    float acc = 0.f;
    for (int m = 0; m < L; m++) {
        int u = g_selmem[k * MAXC + m];
        acc += g_avg[u] * x[(size_t)u * DD + d];
    }
    long long o1 = 2LL * g_Enew;
    out[o1 + (long long)k * DD + d] = acc;
}

// S (0/1) and Ms = S*avg; remainder of region stays zero (memset'd)
__global__ void pk_sms(float* __restrict__ out) {
    int k = blockIdx.x;
    if (k >= g_K) return;
    int m = threadIdx.x;   // 32, guarded by len
    if (m >= g_sellen[k]) return;
    int v = g_selmem[k * MAXC + m];
    long long o2 = 2LL * g_Enew + (long long)g_K * DD;
    out[o2 + (long long)k * NN + v] = 1.0f;
    out[o2 + (long long)g_K * NN + (long long)k * NN + v] = g_avg[v];
}

// edge_index passthrough (int -> float). Region is the LAST 2*EE elements.
__global__ void pk_pass(const int* __restrict__ ei, float* __restrict__ out, long long o4) {
    int t = blockIdx.x * blockDim.x + threadIdx.x;
    if (t >= 2 * EE) return;
    out[o4 + t] = (float)ei[t];
}

// ---------------- launch ----------------
extern "C" void kernel_launch(void* const* d_in, const int* in_sizes, int n_in,
                              void* d_out, int out_size) {
    const float* x  = (const float*)d_in[0];
    const int*   ei = (const int*)d_in[1];
    float* out = (float*)d_out;
    (void)in_sizes; (void)n_in;

    cudaMemsetAsync(d_out, 0, (size_t)out_size * sizeof(float));
    pk_pass<<<512, 256>>>(ei, out, (long long)out_size - 2LL * EE);
    pk_init<<<2048, 256>>>();
    pk_score<<<8192, 256>>>(x, ei);
    pk_rowptr<<<1, 1024>>>();
    pk_scatter<<<256, 256>>>(ei);
    pk_sortavg<<<16, 256>>>();
    pk_grow<<<512, 256>>>(ei);
    pk_dup<<<16, 256>>>();
    pk_rank<<<16, 256>>>();
    pk_invbuild<<<1, 1024>>>();
    pk_greedy<<<1, 1024>>>();
    pk_R<<<4096, 128>>>();
    pk_flags<<<4096, 256>>>();
    pk_finalize<<<1, 1024>>>(out);
    pk_xnew<<<4096, 256>>>(x, out);
    pk_sms<<<4096, 32>>>(out);
}